// round 14
// baseline (speedup 1.0000x reference)
#include <cuda_runtime.h>
#include <cuda_fp16.h>

#define TT    512
#define INSZ  512
#define HH    1024
#define OUTSZ 512
#define NG    4096
#define BSEL  63            // only batch row 63 affects the output
#define NBLK  128
#define NTHR  512
#define SENT  0xFFFFFFFFu   // impossible bit pattern for h in (-1,1)

typedef unsigned long long ull;

// ---------------------------------------------------------------------------
// Static device scratch. Full h histories, sentinel-filled each run:
// the h VALUES are the synchronization (batched polls -> one L2 round trip).
// ---------------------------------------------------------------------------
__device__ __align__(16) float g_h0h[TT + 1][HH];   // h0h[p+1] = h0(p)
__device__ __align__(16) float g_h1h[TT + 1][HH];   // h1h[t+1] = h1(t)
__device__ unsigned g_flags[NBLK * 32];             // init barrier flags
__device__ unsigned g_base = 0u;                    // init-barrier base

// init-only distributed grid barrier (scoped release/acquire)
__device__ __forceinline__ void gridbar(unsigned target) {
    __syncthreads();
    if (threadIdx.x == 0) {
        unsigned* f = &g_flags[blockIdx.x << 5];
        asm volatile("st.release.gpu.u32 [%0], %1;" :: "l"(f), "r"(target) : "memory");
    }
    if (threadIdx.x < NBLK) {
        unsigned* f = &g_flags[threadIdx.x << 5];
        unsigned v;
        do { asm volatile("ld.acquire.gpu.u32 %0, [%1];" : "=r"(v) : "l"(f) : "memory"); }
        while ((int)(v - target) < 0);
    }
    __syncthreads();
}

// Batched sentinel poll: issue all 16 loads (MLP=16), test, retry batch.
// In the ready case this costs ONE L2 round trip and doubles as the data load.
__device__ __forceinline__ void poll16(const ull* hp, int lane, ull v[16]) {
    while (true) {
        #pragma unroll
        for (int i = 0; i < 16; i++)
            asm volatile("ld.relaxed.gpu.global.u64 %0, [%1];"
                         : "=l"(v[i]) : "l"(hp + lane + (i << 5)) : "memory");
        bool ok = true;
        #pragma unroll
        for (int i = 0; i < 16; i++)
            ok &= ((unsigned)v[i] != SENT) && ((unsigned)(v[i] >> 32) != SENT);
        if (ok) break;
    }
}
__device__ __forceinline__ float4 poll_val4(const float4* p) {
    float x, y, z, w;
    while (true) {
        asm volatile("ld.relaxed.gpu.global.v4.f32 {%0,%1,%2,%3}, [%4];"
                     : "=f"(x), "=f"(y), "=f"(z), "=f"(w) : "l"(p) : "memory");
        if (__float_as_uint(x) != SENT && __float_as_uint(y) != SENT &&
            __float_as_uint(z) != SENT && __float_as_uint(w) != SENT) break;
    }
    return make_float4(x, y, z, w);
}
__device__ __forceinline__ void st_rel32(float* p, float v) {
    asm volatile("st.relaxed.gpu.global.f32 [%0], %1;" :: "l"(p), "f"(v) : "memory");
}

// packed fp32x2 FMA (sm_100+) — r10's exact arithmetic (fp32 accumulate)
__device__ __forceinline__ void fma2(ull& a, ull x, ull w) {
    asm("fma.rn.f32x2 %0, %1, %2, %0;" : "+l"(a) : "l"(x), "l"(w));
}
__device__ __forceinline__ ull pk(float a, float b) {
    ull r; asm("mov.b64 %0, {%1, %2};" : "=l"(r) : "f"(a), "f"(b)); return r;
}
__device__ __forceinline__ ull h2f2(__half2 h) {
    float2 f = __half22float2(h);
    return pk(f.x, f.y);
}
__device__ __forceinline__ float upk_sum(ull a) {
    float lo, hi; asm("mov.b64 {%0, %1}, %2;" : "=f"(lo), "=f"(hi) : "l"(a));
    return lo + hi;
}
__device__ __forceinline__ float sigf_(float x) {
    return __fdividef(1.0f, 1.0f + __expf(-x));
}
__device__ __forceinline__ float tanhf_(float x) {
    return 1.0f - __fdividef(2.0f, __expf(2.0f * x) + 1.0f);
}

// shfl-reduce 4 gate partials over the warp, then the LSTM cell update.
__device__ __forceinline__ float cell_tail(ull a0, ull a1, ull a2, ull a3,
                                           float bi, float bj, float bf, float bo,
                                           float& c)
{
    float s0 = upk_sum(a0), s1 = upk_sum(a1), s2 = upk_sum(a2), s3 = upk_sum(a3);
#pragma unroll
    for (int o = 16; o; o >>= 1) {
        s0 += __shfl_xor_sync(0xffffffffu, s0, o);
        s1 += __shfl_xor_sync(0xffffffffu, s1, o);
        s2 += __shfl_xor_sync(0xffffffffu, s2, o);
        s3 += __shfl_xor_sync(0xffffffffu, s3, o);
    }
    float zi = s0 + bi, zj = s1 + bj, zf = s2 + bf + 1.0f, zo = s3 + bo;
    float cn = sigf_(zf) * c + sigf_(zi) * tanhf_(zj);
    c = cn;
    return sigf_(zo) * tanhf_(cn);
}

// SMEM (bytes): W0 fp16 [strip][k] 32x1536 | W1 fp16 32x2048 = 224 KB
#define SM_W0   0
#define SM_W1   98304
#define SM_TOT  229376

__global__ __launch_bounds__(NTHR, 1) void lstm_persistent(
    const float* __restrict__ X,
    const float* __restrict__ state,
    const float* __restrict__ W0, const float* __restrict__ b0,
    const float* __restrict__ W1, const float* __restrict__ b1,
    const float* __restrict__ Wd, const float* __restrict__ bd,
    float* __restrict__ out)
{
    extern __shared__ __align__(16) unsigned char smraw[];
    __half* w0h = (__half*)(smraw + SM_W0);
    __half* w1h = (__half*)(smraw + SM_W1);

    const int tid   = threadIdx.x;
    const int bid   = blockIdx.x;
    const int wid   = tid >> 5;
    const int lane  = tid & 31;
    const int hbase = bid << 3;
    const int jloc  = wid & 7;
    const int hcol  = hbase + jloc;

    const unsigned base = *(volatile unsigned*)&g_base;

    // ---- one-time: pack weights -> SMEM fp16, [strip c][k] ----
    for (int e = tid; e < 32 * 1536; e += NTHR) {
        int c = e & 31, k = e >> 5;
        int col = (c >> 3) * HH + hbase + (c & 7);
        w0h[c * 1536 + k] = __float2half_rn(__ldg(W0 + (size_t)k * NG + col));
    }
    for (int e = tid; e < 32 * 2048; e += NTHR) {
        int c = e & 31, k = e >> 5;
        int col = (c >> 3) * HH + hbase + (c & 7);
        w1h[c * 2048 + k] = __float2half_rn(__ldg(W1 + (size_t)k * NG + col));
    }

    // ---- sentinel-fill h history rows 1..TT (both layers) ----
    {
        const float sf = __uint_as_float(SENT);
        float4 sv = make_float4(sf, sf, sf, sf);
        int gtid = bid * NTHR + tid;
        for (int e = gtid; e < 2 * TT * 256; e += NBLK * NTHR) {
            float4* dst = (e < TT * 256)
                ? (float4*)g_h0h[1 + (e >> 8)] + (e & 255)
                : (float4*)g_h1h[1 + ((e - TT * 256) >> 8)] + (e & 255);
            __stcg(dst, sv);
        }
    }

    // ---- per-warp registers: biases + cell state (state row 63) ----
    const float* srow = state + (size_t)BSEL * 4 * HH;
    const float* bsrc = (wid < 8) ? b0 : b1;
    float bi  = __ldg(bsrc + hcol);
    float bj  = __ldg(bsrc + HH + hcol);
    float bfv = __ldg(bsrc + 2 * HH + hcol);
    float bo  = __ldg(bsrc + 3 * HH + hcol);
    float creg = (wid < 8) ? __ldg(srow + hcol) : __ldg(srow + 2 * HH + hcol);

    if (tid < 8) {
        __stcg(&g_h0h[0][hbase + tid], __ldg(srow + HH + hbase + tid));
        __stcg(&g_h1h[0][hbase + tid], __ldg(srow + 3 * HH + hbase + tid));
    }
    gridbar(base + 1u);   // sentinels + row 0 + weights globally consistent

    const int c0i = jloc, c1i = 8 + jloc, c2i = 16 + jloc, c3i = 24 + jloc;
    const float* Xrow = X + (size_t)BSEL * TT * INSZ;

    if (wid < 8) {
        // ========= layer-0 chain (warps 0-7, no block barriers) =========
        const __half2* s0 = (const __half2*)w0h + c0i * 768;
        const __half2* s1 = (const __half2*)w0h + c1i * 768;
        const __half2* s2 = (const __half2*)w0h + c2i * 768;
        const __half2* s3 = (const __half2*)w0h + c3i * 768;
        for (int p = 0; p < TT; p++) {
            // x-part first: overlaps other blocks' production of h0(p-1)
            ull a0 = 0, a1 = 0, a2 = 0, a3 = 0;
            const ull* xp = (const ull*)(Xrow + (size_t)p * INSZ);
#pragma unroll
            for (int i = 0; i < 8; i++) {
                int idx = lane + (i << 5);
                ull xv = __ldg(xp + idx);
                fma2(a0, xv, h2f2(s0[idx]));
                fma2(a1, xv, h2f2(s1[idx]));
                fma2(a2, xv, h2f2(s2[idx]));
                fma2(a3, xv, h2f2(s3[idx]));
            }
            // h-part: batched sentinel poll == detection + data in one round
            ull v[16];
            poll16((const ull*)g_h0h[p], lane, v);
#pragma unroll
            for (int i = 0; i < 16; i++) {
                int idx = lane + (i << 5);
                fma2(a0, v[i], h2f2(s0[256 + idx]));
                fma2(a1, v[i], h2f2(s1[256 + idx]));
                fma2(a2, v[i], h2f2(s2[256 + idx]));
                fma2(a3, v[i], h2f2(s3[256 + idx]));
            }
            float h = cell_tail(a0, a1, a2, a3, bi, bj, bfv, bo, creg);
            if (lane == 0) st_rel32(&g_h0h[p + 1][hcol], h);
        }
    } else {
        // ========= layer-1 chain (warps 8-15, no block barriers) =========
        const __half2* s0 = (const __half2*)w1h + c0i * 1024;
        const __half2* s1 = (const __half2*)w1h + c1i * 1024;
        const __half2* s2 = (const __half2*)w1h + c2i * 1024;
        const __half2* s3 = (const __half2*)w1h + c3i * 1024;
        for (int t = 0; t < TT; t++) {
            ull a0 = 0, a1 = 0, a2 = 0, a3 = 0;
            ull v[16];
            poll16((const ull*)g_h0h[t + 1], lane, v);
#pragma unroll
            for (int i = 0; i < 16; i++) {
                int idx = lane + (i << 5);
                fma2(a0, v[i], h2f2(s0[idx]));
                fma2(a1, v[i], h2f2(s1[idx]));
                fma2(a2, v[i], h2f2(s2[idx]));
                fma2(a3, v[i], h2f2(s3[idx]));
            }
            poll16((const ull*)g_h1h[t], lane, v);
#pragma unroll
            for (int i = 0; i < 16; i++) {
                int idx = lane + (i << 5);
                fma2(a0, v[i], h2f2(s0[512 + idx]));
                fma2(a1, v[i], h2f2(s1[512 + idx]));
                fma2(a2, v[i], h2f2(s2[512 + idx]));
                fma2(a3, v[i], h2f2(s3[512 + idx]));
            }
            float h = cell_tail(a0, a1, a2, a3, bi, bj, bfv, bo, creg);
            if (lane == 0) st_rel32(&g_h1h[t + 1][hcol], h);
        }
    }

    __syncthreads();   // block convergence before SMEM reuse (w0h region only)

    // ---- dense: out[t][o] = h1(t) @ Wd + bd; block owns 4 t-rows ----
    {
        float* hst = (float*)smraw;          // 16KB, overlaps w0h only
        int t0q = bid << 2;
        for (int e = tid; e < 1024; e += NTHR)
            ((float4*)hst)[e] =
                poll_val4((const float4*)g_h1h[t0q + (e >> 8) + 1] + (e & 255));
        __syncthreads();

        int r  = tid >> 7;                   // 0..3
        int o0 = (tid & 127) << 2;           // 0..508
        float4 acc = make_float4(__ldg(bd + o0), __ldg(bd + o0 + 1),
                                 __ldg(bd + o0 + 2), __ldg(bd + o0 + 3));
        const float* hrow = hst + (r << 10);
        const float* wp = Wd + o0;
#pragma unroll 8
        for (int k = 0; k < HH; k++) {
            float4 w4 = __ldcg((const float4*)wp);
            wp += OUTSZ;
            acc.x = fmaf(hrow[k], w4.x, acc.x);
            acc.y = fmaf(hrow[k], w4.y, acc.y);
            acc.z = fmaf(hrow[k], w4.z, acc.z);
            acc.w = fmaf(hrow[k], w4.w, acc.w);
        }
        *(float4*)(out + (size_t)(t0q + r) * OUTSZ + o0) = acc;
    }

    // advance the init-barrier base for the next graph replay
    if (bid == 0 && tid == 0)
        *(volatile unsigned*)&g_base = base + 2u;
}

// ---------------------------------------------------------------------------
// Launcher: ONE kernel launch, 224KB dynamic smem opted in.
// ---------------------------------------------------------------------------
extern "C" void kernel_launch(void* const* d_in, const int* in_sizes, int n_in,
                              void* d_out, int out_size)
{
    (void)in_sizes; (void)n_in; (void)out_size;
    const float* X     = (const float*)d_in[0];
    const float* state = (const float*)d_in[1];
    const float* W0    = (const float*)d_in[2];
    const float* b0    = (const float*)d_in[3];
    const float* W1    = (const float*)d_in[4];
    const float* b1    = (const float*)d_in[5];
    const float* Wd    = (const float*)d_in[6];
    const float* bd    = (const float*)d_in[7];

    static int configured = 0;
    if (!configured) {
        cudaFuncSetAttribute(lstm_persistent,
                             cudaFuncAttributeMaxDynamicSharedMemorySize,
                             SM_TOT);
        configured = 1;
    }

    lstm_persistent<<<NBLK, NTHR, SM_TOT>>>(
        X, state, W0, b0, W1, b1, Wd, bd, (float*)d_out);
}

// round 15
// speedup vs baseline: 4.1117x; 4.1117x over previous
#include <cuda_runtime.h>
#include <cuda_fp16.h>

#define TT    512
#define INSZ  512
#define HH    1024
#define OUTSZ 512
#define NG    4096
#define BSEL  63            // only batch row 63 affects the output
#define NBLK  128
#define L0B   64            // blocks 0..63: layer-0 role; 64..127: layer-1 role
#define NTHR  512

typedef unsigned long long ull;

// ---------------------------------------------------------------------------
// Static device scratch.
// ---------------------------------------------------------------------------
__device__ __align__(16) float g_h0h[TT + 1][HH];   // h0h[p+1] = h0(p)
__device__ __align__(16) float g_h1h[TT + 1][HH];   // h1h[t+1] = h1(t)
__device__ __half   g_W1p[(size_t)L0B * 64 * 1024]; // packed W1 h1-half (8.4MB)
__device__ unsigned g_cA[TT][256];                  // h0(p) ready: 8 lines/phase
__device__ unsigned g_cB[TT][256];                  // h1(t) ready: 8 lines/phase
__device__ unsigned g_flags[NBLK * 32];             // init barrier flags
__device__ unsigned g_base = 0u;
__device__ unsigned g_rep  = 0u;                    // +=8 per replay

// init-only distributed grid barrier (scoped release/acquire)
__device__ __forceinline__ void gridbar(unsigned target) {
    __syncthreads();
    if (threadIdx.x == 0) {
        unsigned* f = &g_flags[blockIdx.x << 5];
        asm volatile("st.release.gpu.u32 [%0], %1;" :: "l"(f), "r"(target) : "memory");
    }
    if (threadIdx.x < NBLK) {
        unsigned* f = &g_flags[threadIdx.x << 5];
        unsigned v;
        do { asm volatile("ld.acquire.gpu.u32 %0, [%1];" : "=r"(v) : "l"(f) : "memory"); }
        while ((int)(v - target) < 0);
    }
    __syncthreads();
}
__device__ __forceinline__ void poll_ctr(const unsigned* c, unsigned target) {
    unsigned v;
    do { asm volatile("ld.acquire.gpu.u32 %0, [%1];" : "=r"(v) : "l"(c) : "memory"); }
    while ((int)(v - target) < 0);
}
__device__ __forceinline__ void bump_ctr(unsigned* c) {
    asm volatile("red.release.gpu.global.add.u32 [%0], 1;" :: "l"(c) : "memory");
}

// packed fp32x2 FMA (sm_100+) — fp32 accumulate (r10's exact arithmetic)
__device__ __forceinline__ void fma2(ull& a, ull x, ull w) {
    asm("fma.rn.f32x2 %0, %1, %2, %0;" : "+l"(a) : "l"(x), "l"(w));
}
__device__ __forceinline__ ull pk(float a, float b) {
    ull r; asm("mov.b64 %0, {%1, %2};" : "=l"(r) : "f"(a), "f"(b)); return r;
}
__device__ __forceinline__ ull h2f2(__half2 h) {
    float2 f = __half22float2(h);
    return pk(f.x, f.y);
}
__device__ __forceinline__ float upk_sum(ull a) {
    float lo, hi; asm("mov.b64 {%0, %1}, %2;" : "=f"(lo), "=f"(hi) : "l"(a));
    return lo + hi;
}
__device__ __forceinline__ float sigf_(float x) {
    return __fdividef(1.0f, 1.0f + __expf(-x));
}
__device__ __forceinline__ float tanhf_(float x) {
    return 1.0f - __fdividef(2.0f, __expf(2.0f * x) + 1.0f);
}

// shfl-reduce 4 gate partials over the warp, then the LSTM cell update.
__device__ __forceinline__ float cell_tail(ull a0, ull a1, ull a2, ull a3,
                                           float bi, float bj, float bf, float bo,
                                           float& c)
{
    float s0 = upk_sum(a0), s1 = upk_sum(a1), s2 = upk_sum(a2), s3 = upk_sum(a3);
#pragma unroll
    for (int o = 16; o; o >>= 1) {
        s0 += __shfl_xor_sync(0xffffffffu, s0, o);
        s1 += __shfl_xor_sync(0xffffffffu, s1, o);
        s2 += __shfl_xor_sync(0xffffffffu, s2, o);
        s3 += __shfl_xor_sync(0xffffffffu, s3, o);
    }
    float zi = s0 + bi, zj = s1 + bj, zf = s2 + bf + 1.0f, zo = s3 + bo;
    float cn = sigf_(zf) * c + sigf_(zi) * tanhf_(zj);
    c = cn;
    return sigf_(zo) * tanhf_(cn);
}

// Dynamic SMEM: L0 blocks: W0 fp16 [64 strips][1536] = 196608 B
//               L1 blocks: W1 h0-half fp16 [64 strips][1024] = 131072 B
#define SM_TOT  196608

__global__ __launch_bounds__(NTHR, 1) void lstm_persistent(
    const float* __restrict__ X,
    const float* __restrict__ state,
    const float* __restrict__ W0, const float* __restrict__ b0,
    const float* __restrict__ W1, const float* __restrict__ b1,
    const float* __restrict__ Wd, const float* __restrict__ bd,
    float* __restrict__ out)
{
    extern __shared__ __align__(16) unsigned char smraw[];
    __half* wsh = (__half*)smraw;

    const int tid  = threadIdx.x;
    const int bid  = blockIdx.x;
    const int wid  = tid >> 5;
    const int lane = tid & 31;
    const bool isL0 = (bid < L0B);
    const int blk  = isL0 ? bid : (bid - L0B);
    const int hb   = blk << 4;          // this block's 16 h-columns
    const int hcol = hb + wid;          // warp wid owns one h-column

    const unsigned base = *(volatile unsigned*)&g_base;
    const unsigned rep  = *(volatile unsigned*)&g_rep;
    const unsigned TGT  = rep + 8u;     // per-counter-line arrival target

    const float* srow = state + (size_t)BSEL * 4 * HH;

    // ---- one-time packing + state init (role-dependent) ----
    if (isL0) {
        for (int e = tid; e < 64 * 1536; e += NTHR) {
            int c = e & 63, k = e >> 6;
            int col = (c >> 4) * HH + hb + (c & 15);
            wsh[c * 1536 + k] = __float2half_rn(__ldg(W0 + (size_t)k * NG + col));
        }
        if (tid < 16)
            __stcg(&g_h0h[0][hb + tid], __ldg(srow + HH + hb + tid));
    } else {
        for (int e = tid; e < 64 * 1024; e += NTHR) {
            int c = e & 63, k = e >> 6;
            int col = (c >> 4) * HH + hb + (c & 15);
            wsh[c * 1024 + k] = __float2half_rn(__ldg(W1 + (size_t)k * NG + col));
            g_W1p[((size_t)blk * 64 + c) * 1024 + k] =
                __float2half_rn(__ldg(W1 + (size_t)(1024 + k) * NG + col));
        }
        if (tid < 16)
            __stcg(&g_h1h[0][hb + tid], __ldg(srow + 3 * HH + hb + tid));
    }

    // per-warp biases + cell state
    const float* bsrc = isL0 ? b0 : b1;
    float bi  = __ldg(bsrc + hcol);
    float bj  = __ldg(bsrc + HH + hcol);
    float bfv = __ldg(bsrc + 2 * HH + hcol);
    float bo  = __ldg(bsrc + 3 * HH + hcol);
    float creg = isL0 ? __ldg(srow + hcol) : __ldg(srow + 2 * HH + hcol);

    gridbar(base + 1u);   // packs + initial h rows globally visible

    // strip indices: gate g strip = g*16 + wid
    const int cI = wid, cJ = 16 + wid, cF = 32 + wid, cO = 48 + wid;
    const float* Xrow = X + (size_t)BSEL * TT * INSZ;

    if (isL0) {
        // ================= layer-0 role (blocks 0..63) =================
        const __half2* s0 = (const __half2*)wsh + cI * 768;
        const __half2* s1 = (const __half2*)wsh + cJ * 768;
        const __half2* s2 = (const __half2*)wsh + cF * 768;
        const __half2* s3 = (const __half2*)wsh + cO * 768;
        for (int p = 0; p < TT; p++) {
            // x-part first: no cross-block dependency, overlaps producer wait
            ull a0 = 0, a1 = 0, a2 = 0, a3 = 0;
            const ull* xp = (const ull*)(Xrow + (size_t)p * INSZ);
#pragma unroll
            for (int i = 0; i < 8; i++) {
                int idx = lane + (i << 5);
                ull xv = __ldg(xp + idx);
                fma2(a0, xv, h2f2(s0[idx]));
                fma2(a1, xv, h2f2(s1[idx]));
                fma2(a2, xv, h2f2(s2[idx]));
                fma2(a3, xv, h2f2(s3[idx]));
            }
            // detect h0(p-1): 8 threads poll 8 distinct counter lines
            if (p > 0 && tid < 8) poll_ctr(&g_cA[p - 1][tid << 5], TGT);
            __syncthreads();
            const ull* hp = (const ull*)g_h0h[p];
#pragma unroll
            for (int i = 0; i < 16; i++) {
                int idx = lane + (i << 5);
                ull xv = __ldcg(hp + idx);
                fma2(a0, xv, h2f2(s0[256 + idx]));
                fma2(a1, xv, h2f2(s1[256 + idx]));
                fma2(a2, xv, h2f2(s2[256 + idx]));
                fma2(a3, xv, h2f2(s3[256 + idx]));
            }
            float h = cell_tail(a0, a1, a2, a3, bi, bj, bfv, bo, creg);
            if (lane == 0) __stcg(&g_h0h[p + 1][hcol], h);
            __syncthreads();    // all 16 h-cols of this block stored
            if (tid == 0) bump_ctr(&g_cA[p][(bid & 7) << 5]);
        }
    } else {
        // ================= layer-1 role (blocks 64..127) =================
        const __half2* s0 = (const __half2*)wsh + cI * 512;
        const __half2* s1 = (const __half2*)wsh + cJ * 512;
        const __half2* s2 = (const __half2*)wsh + cF * 512;
        const __half2* s3 = (const __half2*)wsh + cO * 512;
        const __half2* g0 = (const __half2*)(g_W1p + ((size_t)blk * 64 + cI) * 1024);
        const __half2* g1 = (const __half2*)(g_W1p + ((size_t)blk * 64 + cJ) * 1024);
        const __half2* g2 = (const __half2*)(g_W1p + ((size_t)blk * 64 + cF) * 1024);
        const __half2* g3 = (const __half2*)(g_W1p + ((size_t)blk * 64 + cO) * 1024);
        for (int t = 0; t < TT; t++) {
            // detect h0(t) and h1(t-1): 16 threads poll 16 distinct lines
            if (tid < 8) poll_ctr(&g_cA[t][tid << 5], TGT);
            else if (tid < 16 && t > 0) poll_ctr(&g_cB[t - 1][(tid - 8) << 5], TGT);
            __syncthreads();

            ull a0 = 0, a1 = 0, a2 = 0, a3 = 0;
            const ull* hp0 = (const ull*)g_h0h[t + 1];
#pragma unroll
            for (int i = 0; i < 16; i++) {
                int idx = lane + (i << 5);
                ull xv = __ldcg(hp0 + idx);
                fma2(a0, xv, h2f2(s0[idx]));
                fma2(a1, xv, h2f2(s1[idx]));
                fma2(a2, xv, h2f2(s2[idx]));
                fma2(a3, xv, h2f2(s3[idx]));
            }
            const ull* hp1 = (const ull*)g_h1h[t];
#pragma unroll
            for (int i = 0; i < 16; i++) {
                int idx = lane + (i << 5);
                ull xv = __ldcg(hp1 + idx);
                fma2(a0, xv, h2f2(__ldg(g0 + idx)));
                fma2(a1, xv, h2f2(__ldg(g1 + idx)));
                fma2(a2, xv, h2f2(__ldg(g2 + idx)));
                fma2(a3, xv, h2f2(__ldg(g3 + idx)));
            }
            float h = cell_tail(a0, a1, a2, a3, bi, bj, bfv, bo, creg);
            if (lane == 0) __stcg(&g_h1h[t + 1][hcol], h);
            __syncthreads();
            if (tid == 0) bump_ctr(&g_cB[t][(blk & 7) << 5]);
        }
    }

    // ---- wait for full h1 history, then the dense tail ----
    if (tid < 8) poll_ctr(&g_cB[TT - 1][tid << 5], TGT);
    __syncthreads();

    // dense: out[t][o] = h1(t) @ Wd + bd; block owns 4 t-rows
    {
        float* hst = (float*)smraw;          // reuse weight region (16KB)
        int t0q = bid << 2;
        for (int e = tid; e < 1024; e += NTHR)
            ((float4*)hst)[e] =
                __ldcg((const float4*)g_h1h[t0q + (e >> 8) + 1] + (e & 255));
        __syncthreads();

        int r  = tid >> 7;
        int o0 = (tid & 127) << 2;
        float4 acc = make_float4(__ldg(bd + o0), __ldg(bd + o0 + 1),
                                 __ldg(bd + o0 + 2), __ldg(bd + o0 + 3));
        const float* hrow = hst + (r << 10);
        const float* wp = Wd + o0;
#pragma unroll 8
        for (int k = 0; k < HH; k++) {
            float4 w4 = __ldcg((const float4*)wp);
            wp += OUTSZ;
            acc.x = fmaf(hrow[k], w4.x, acc.x);
            acc.y = fmaf(hrow[k], w4.y, acc.y);
            acc.z = fmaf(hrow[k], w4.z, acc.z);
            acc.w = fmaf(hrow[k], w4.w, acc.w);
        }
        *(float4*)(out + (size_t)(t0q + r) * OUTSZ + o0) = acc;
    }

    // advance persistent bases for the next graph replay
    if (bid == 0 && tid == 0) {
        *(volatile unsigned*)&g_rep  = rep + 8u;
        *(volatile unsigned*)&g_base = base + 2u;
    }
}

// ---------------------------------------------------------------------------
// Launcher: ONE kernel launch, 192KB dynamic smem opted in.
// ---------------------------------------------------------------------------
extern "C" void kernel_launch(void* const* d_in, const int* in_sizes, int n_in,
                              void* d_out, int out_size)
{
    (void)in_sizes; (void)n_in; (void)out_size;
    const float* X     = (const float*)d_in[0];
    const float* state = (const float*)d_in[1];
    const float* W0    = (const float*)d_in[2];
    const float* b0    = (const float*)d_in[3];
    const float* W1    = (const float*)d_in[4];
    const float* b1    = (const float*)d_in[5];
    const float* Wd    = (const float*)d_in[6];
    const float* bd    = (const float*)d_in[7];

    static int configured = 0;
    if (!configured) {
        cudaFuncSetAttribute(lstm_persistent,
                             cudaFuncAttributeMaxDynamicSharedMemorySize,
                             SM_TOT);
        configured = 1;
    }

    lstm_persistent<<<NBLK, NTHR, SM_TOT>>>(
        X, state, W0, b0, W1, b1, Wd, bd, (float*)d_out);
}

// round 16
// speedup vs baseline: 5.4524x; 1.3261x over previous
#include <cuda_runtime.h>
#include <cuda_fp16.h>

#define TT    512
#define INSZ  512
#define HH    1024
#define OUTSZ 512
#define NG    4096
#define BSEL  63            // only batch row 63 affects the output
#define NBLK  128
#define NTHR  512
#define NLINES 16           // arrival counter lines per phase (8 blocks each)

typedef unsigned long long ull;

// ---------------------------------------------------------------------------
// Static device scratch (r10 skeleton; counters split 16-way per phase).
// ---------------------------------------------------------------------------
__device__ __align__(16) float g_h0h[TT + 1][HH];   // h0h[p+1] = h0(p)
__device__ __align__(16) float g_h1h[TT + 1][HH];   // h1h[t+1] = h1(t)
__device__ unsigned g_c0[TT][NLINES * 32];          // h0(p) arrivals, 16 lines
__device__ unsigned g_c1[TT][NLINES * 32];          // h1(t) arrivals, 16 lines
__device__ unsigned g_flags[NBLK * 32];             // init barrier flags
__device__ unsigned g_base = 0u;
__device__ unsigned g_rep  = 0u;                    // +=8 per replay

__device__ __forceinline__ void gridbar(unsigned target) {
    __syncthreads();
    if (threadIdx.x == 0) {
        unsigned* f = &g_flags[blockIdx.x << 5];
        asm volatile("st.release.gpu.u32 [%0], %1;" :: "l"(f), "r"(target) : "memory");
    }
    if (threadIdx.x < NBLK) {
        unsigned* f = &g_flags[threadIdx.x << 5];
        unsigned v;
        do { asm volatile("ld.acquire.gpu.u32 %0, [%1];" : "=r"(v) : "l"(f) : "memory"); }
        while ((int)(v - target) < 0);
    }
    __syncthreads();
}
__device__ __forceinline__ void poll_ctr(const unsigned* c, unsigned target) {
    unsigned v;
    do { asm volatile("ld.acquire.gpu.u32 %0, [%1];" : "=r"(v) : "l"(c) : "memory"); }
    while ((int)(v - target) < 0);
}
__device__ __forceinline__ void bump_ctr(unsigned* c) {
    asm volatile("red.release.gpu.global.add.u32 [%0], 1;" :: "l"(c) : "memory");
}

// packed fp32x2 FMA (sm_100+) — fp32 accumulate (r10's exact arithmetic)
__device__ __forceinline__ void fma2(ull& a, ull x, ull w) {
    asm("fma.rn.f32x2 %0, %1, %2, %0;" : "+l"(a) : "l"(x), "l"(w));
}
__device__ __forceinline__ ull pk(float a, float b) {
    ull r; asm("mov.b64 %0, {%1, %2};" : "=l"(r) : "f"(a), "f"(b)); return r;
}
__device__ __forceinline__ ull h2f2(__half2 h) {
    float2 f = __half22float2(h);
    return pk(f.x, f.y);
}
__device__ __forceinline__ float upk_sum(ull a) {
    float lo, hi; asm("mov.b64 {%0, %1}, %2;" : "=f"(lo), "=f"(hi) : "l"(a));
    return lo + hi;
}
__device__ __forceinline__ float sigf_(float x) {
    return __fdividef(1.0f, 1.0f + __expf(-x));
}
__device__ __forceinline__ float tanhf_(float x) {
    return 1.0f - __fdividef(2.0f, __expf(2.0f * x) + 1.0f);
}

// shfl-reduce 4 gate partials over the warp, then the LSTM cell update.
__device__ __forceinline__ float cell_tail(ull a0, ull a1, ull a2, ull a3,
                                           float bi, float bj, float bf, float bo,
                                           float& c)
{
    float s0 = upk_sum(a0), s1 = upk_sum(a1), s2 = upk_sum(a2), s3 = upk_sum(a3);
#pragma unroll
    for (int o = 16; o; o >>= 1) {
        s0 += __shfl_xor_sync(0xffffffffu, s0, o);
        s1 += __shfl_xor_sync(0xffffffffu, s1, o);
        s2 += __shfl_xor_sync(0xffffffffu, s2, o);
        s3 += __shfl_xor_sync(0xffffffffu, s3, o);
    }
    float zi = s0 + bi, zj = s1 + bj, zf = s2 + bf + 1.0f, zo = s3 + bo;
    float cn = sigf_(zf) * c + sigf_(zi) * tanhf_(zj);
    c = cn;
    return sigf_(zo) * tanhf_(cn);
}

// SMEM (bytes): W0 fp16 [strip][k] 32x1536 | W1 fp16 32x2048 = 224 KB
#define SM_W0   0
#define SM_W1   98304
#define SM_TOT  229376

__global__ __launch_bounds__(NTHR, 1) void lstm_persistent(
    const float* __restrict__ X,
    const float* __restrict__ state,
    const float* __restrict__ W0, const float* __restrict__ b0,
    const float* __restrict__ W1, const float* __restrict__ b1,
    const float* __restrict__ Wd, const float* __restrict__ bd,
    float* __restrict__ out)
{
    extern __shared__ __align__(16) unsigned char smraw[];
    __half* w0h = (__half*)(smraw + SM_W0);
    __half* w1h = (__half*)(smraw + SM_W1);

    const int tid   = threadIdx.x;
    const int bid   = blockIdx.x;
    const int wid   = tid >> 5;
    const int lane  = tid & 31;
    const int hbase = bid << 3;
    const int jloc  = wid & 7;
    const int hcol  = hbase + jloc;

    const unsigned base = *(volatile unsigned*)&g_base;
    const unsigned rep  = *(volatile unsigned*)&g_rep;
    const unsigned TGT  = rep + 8u;      // 8 blocks arrive per counter line

    // ---- one-time: pack weights -> SMEM fp16, [strip c][k] ----
    for (int e = tid; e < 32 * 1536; e += NTHR) {
        int c = e & 31, k = e >> 5;
        int col = (c >> 3) * HH + hbase + (c & 7);
        w0h[c * 1536 + k] = __float2half_rn(__ldg(W0 + (size_t)k * NG + col));
    }
    for (int e = tid; e < 32 * 2048; e += NTHR) {
        int c = e & 31, k = e >> 5;
        int col = (c >> 3) * HH + hbase + (c & 7);
        w1h[c * 2048 + k] = __float2half_rn(__ldg(W1 + (size_t)k * NG + col));
    }

    // ---- per-warp registers: biases + cell state (state row 63) ----
    const float* srow = state + (size_t)BSEL * 4 * HH;
    const float* bsrc = (wid < 8) ? b0 : b1;
    float bi  = __ldg(bsrc + hcol);
    float bj  = __ldg(bsrc + HH + hcol);
    float bfv = __ldg(bsrc + 2 * HH + hcol);
    float bo  = __ldg(bsrc + 3 * HH + hcol);
    float creg = (wid < 8) ? __ldg(srow + hcol) : __ldg(srow + 2 * HH + hcol);

    if (tid < 8) {
        __stcg(&g_h0h[0][hbase + tid], __ldg(srow + HH + hbase + tid));
        __stcg(&g_h1h[0][hbase + tid], __ldg(srow + 3 * HH + hbase + tid));
    }
    gridbar(base + 1u);

    const int c0i = jloc, c1i = 8 + jloc, c2i = 16 + jloc, c3i = 24 + jloc;
    const float* Xrow = X + (size_t)BSEL * TT * INSZ;

    if (wid < 8) {
        // =================== layer-0 chain (warps 0-7) ===================
        const __half2* s0 = (const __half2*)w0h + c0i * 768;
        const __half2* s1 = (const __half2*)w0h + c1i * 768;
        const __half2* s2 = (const __half2*)w0h + c2i * 768;
        const __half2* s3 = (const __half2*)w0h + c3i * 768;
        for (int p = 0; p < TT; p++) {
            // x-part: independent -> overlaps producer wait
            ull a0 = 0, a1 = 0, a2 = 0, a3 = 0;
            const ull* xp = (const ull*)(Xrow + (size_t)p * INSZ);
#pragma unroll
            for (int i = 0; i < 8; i++) {
                int idx = lane + (i << 5);
                ull xv = __ldg(xp + idx);
                fma2(a0, xv, h2f2(s0[idx]));
                fma2(a1, xv, h2f2(s1[idx]));
                fma2(a2, xv, h2f2(s2[idx]));
                fma2(a3, xv, h2f2(s3[idx]));
            }
            // wait for h0(p-1): 16 threads poll 16 distinct counter lines
            if (p > 0 && tid < NLINES) poll_ctr(&g_c0[p - 1][tid << 5], TGT);
            asm volatile("bar.sync 1, 256;" ::: "memory");
            const ull* hp = (const ull*)g_h0h[p];
#pragma unroll
            for (int i = 0; i < 16; i++) {
                int idx = lane + (i << 5);
                ull xv = __ldcg(hp + idx);
                fma2(a0, xv, h2f2(s0[256 + idx]));
                fma2(a1, xv, h2f2(s1[256 + idx]));
                fma2(a2, xv, h2f2(s2[256 + idx]));
                fma2(a3, xv, h2f2(s3[256 + idx]));
            }
            float h = cell_tail(a0, a1, a2, a3, bi, bj, bfv, bo, creg);
            if (lane == 0) __stcg(&g_h0h[p + 1][hcol], h);
            asm volatile("bar.sync 1, 256;" ::: "memory");
            if (tid == 0) bump_ctr(&g_c0[p][(bid & (NLINES - 1)) << 5]);
        }
    } else {
        // =================== layer-1 chain (warps 8-15) ==================
        const __half2* s0 = (const __half2*)w1h + c0i * 1024;
        const __half2* s1 = (const __half2*)w1h + c1i * 1024;
        const __half2* s2 = (const __half2*)w1h + c2i * 1024;
        const __half2* s3 = (const __half2*)w1h + c3i * 1024;
        for (int t = 0; t < TT; t++) {
            // wait: h0(t) lines (threads 256-271), h1(t-1) lines (272-287)
            if (tid >= 256 && tid < 256 + NLINES)
                poll_ctr(&g_c0[t][(tid - 256) << 5], TGT);
            else if (tid >= 256 + NLINES && tid < 256 + 2 * NLINES && t > 0)
                poll_ctr(&g_c1[t - 1][(tid - 256 - NLINES) << 5], TGT);
            asm volatile("bar.sync 2, 256;" ::: "memory");

            ull a0 = 0, a1 = 0, a2 = 0, a3 = 0;
            const ull* hp0 = (const ull*)g_h0h[t + 1];
#pragma unroll
            for (int i = 0; i < 16; i++) {
                int idx = lane + (i << 5);
                ull xv = __ldcg(hp0 + idx);
                fma2(a0, xv, h2f2(s0[idx]));
                fma2(a1, xv, h2f2(s1[idx]));
                fma2(a2, xv, h2f2(s2[idx]));
                fma2(a3, xv, h2f2(s3[idx]));
            }
            const ull* hp1 = (const ull*)g_h1h[t];
#pragma unroll
            for (int i = 0; i < 16; i++) {
                int idx = lane + (i << 5);
                ull xv = __ldcg(hp1 + idx);
                fma2(a0, xv, h2f2(s0[512 + idx]));
                fma2(a1, xv, h2f2(s1[512 + idx]));
                fma2(a2, xv, h2f2(s2[512 + idx]));
                fma2(a3, xv, h2f2(s3[512 + idx]));
            }
            float h = cell_tail(a0, a1, a2, a3, bi, bj, bfv, bo, creg);
            if (lane == 0) __stcg(&g_h1h[t + 1][hcol], h);
            asm volatile("bar.sync 2, 256;" ::: "memory");
            if (tid == 256) bump_ctr(&g_c1[t][(bid & (NLINES - 1)) << 5]);
        }
    }

    // ---- global completion of layer-1 before the dense tail ----
    if (tid < NLINES) poll_ctr(&g_c1[TT - 1][tid << 5], TGT);
    __syncthreads();

    // ---- dense: out[t][o] = h1(t) @ Wd + bd; block owns 4 t-rows ----
    {
        float* hst = (float*)smraw;          // reuse weight region (16KB)
        int t0q = bid << 2;
        for (int e = tid; e < 1024; e += NTHR)
            ((float4*)hst)[e] =
                __ldcg((const float4*)g_h1h[t0q + (e >> 8) + 1] + (e & 255));
        __syncthreads();

        int r  = tid >> 7;
        int o0 = (tid & 127) << 2;
        float4 acc = make_float4(__ldg(bd + o0), __ldg(bd + o0 + 1),
                                 __ldg(bd + o0 + 2), __ldg(bd + o0 + 3));
        const float* hrow = hst + (r << 10);
        const float* wp = Wd + o0;
#pragma unroll 8
        for (int k = 0; k < HH; k++) {
            float4 w4 = __ldcg((const float4*)wp);
            wp += OUTSZ;
            acc.x = fmaf(hrow[k], w4.x, acc.x);
            acc.y = fmaf(hrow[k], w4.y, acc.y);
            acc.z = fmaf(hrow[k], w4.z, acc.z);
            acc.w = fmaf(hrow[k], w4.w, acc.w);
        }
        *(float4*)(out + (size_t)(t0q + r) * OUTSZ + o0) = acc;
    }

    // advance persistent bases for the next graph replay
    if (bid == 0 && tid == 0) {
        *(volatile unsigned*)&g_rep  = rep + 8u;
        *(volatile unsigned*)&g_base = base + 2u;
    }
}

// ---------------------------------------------------------------------------
// Launcher: ONE kernel launch, 224KB dynamic smem opted in.
// ---------------------------------------------------------------------------
extern "C" void kernel_launch(void* const* d_in, const int* in_sizes, int n_in,
                              void* d_out, int out_size)
{
    (void)in_sizes; (void)n_in; (void)out_size;
    const float* X     = (const float*)d_in[0];
    const float* state = (const float*)d_in[1];
    const float* W0    = (const float*)d_in[2];
    const float* b0    = (const float*)d_in[3];
    const float* W1    = (const float*)d_in[4];
    const float* b1    = (const float*)d_in[5];
    const float* Wd    = (const float*)d_in[6];
    const float* bd    = (const float*)d_in[7];

    static int configured = 0;
    if (!configured) {
        cudaFuncSetAttribute(lstm_persistent,
                             cudaFuncAttributeMaxDynamicSharedMemorySize,
                             SM_TOT);
        configured = 1;
    }

    lstm_persistent<<<NBLK, NTHR, SM_TOT>>>(
        X, state, W0, b0, W1, b1, Wd, bd, (float*)d_out);
}